// round 13
// baseline (speedup 1.0000x reference)
#include <cuda_runtime.h>
#include <cuda_fp16.h>
#include <stdint.h>
#include <math.h>

#define Bc   4
#define C    48
#define C3   144
#define HH   256
#define WW   256
#define NPIX 65536   // HH*WW

typedef unsigned long long u64;
typedef unsigned int u32;

__device__ __forceinline__ u32 smem_u32(const void* p) {
    return (u32)__cvta_generic_to_shared(p);
}

// ---- scratch (device globals: no allocation allowed) ----
__device__ __half g_dw [(size_t)Bc * C3 * NPIX];
__device__ float  g_small[Bc * (C * C + 2 * C)];
__device__ float  g_M[Bc * C * C];

// ============================================================
// K1 (fused): 1x1 qkv conv (HMMA) + 3x3 depthwise, g_qkv never
// touches HBM. Block = 4 out rows x 128 out cols (+1 halo each side).
// Xs: x fp16 [48][6 segs * 136], pitch 824 (1648B = 103*16B odd).
// Per 16-oc chunk: HMMA -> Qb[16][824] -> depthwise -> g_dw.
// ============================================================
#define XPITCH 824
#define SEG    136
#define NT     102   // n-tiles of 8 px: 6 segs * 17
__global__ void __launch_bounds__(288) k_fused(const float* __restrict__ x,
                                               const float* __restrict__ wqkv,
                                               const float* __restrict__ wdw) {
    extern __shared__ __align__(16) char sm[];
    __half* Xs  = (__half*)sm;                    // 48*824
    __half* Qb  = Xs + 48 * XPITCH;               // 16*824
    __half* Ws  = Qb + 16 * XPITCH;               // 144*56
    float*  dww = (float*)(Ws + 144 * 56);        // 144

    const int tid  = threadIdx.x;
    const int warp = tid >> 5, lane = tid & 31;
    const int b    = blockIdx.x >> 7;             // 128 blocks / batch
    const int rem  = blockIdx.x & 127;
    const int y0   = (rem >> 1) * 4;
    const int x0   = (rem & 1) * 128;

    // stage W (row-major [oc][k], pitch 56)
    for (int i = tid; i < C3 * C; i += 288)
        Ws[(i / C) * 56 + (i % C)] = __float2half_rn(wqkv[i]);

    // stage x with halo, zero pad outside image
    const float* xb = x + (size_t)b * C * NPIX;
    for (int i = tid; i < C * 816; i += 288) {
        int k = i / 816, r = i % 816;
        int seg = r / SEG, c = r % SEG;
        int gy = y0 - 1 + seg, gx = x0 - 1 + c;
        float v = (gy >= 0 && gy < HH && gx >= 0 && gx < WW)
                  ? xb[(size_t)k * NPIX + gy * WW + gx] : 0.f;
        Xs[k * XPITCH + seg * SEG + c] = __float2half_rn(v);
    }
    __syncthreads();

    const int g = lane >> 2, t = lane & 3;

#pragma unroll 1
    for (int chunk = 0; chunk < 9; chunk++) {
        // depthwise weights for this chunk's 16 channels
        if (tid < 144) dww[tid] = wdw[chunk * 144 + tid];

        // A fragments for m-tile = chunk
        const int m0 = chunk * 16;
        u32 a[3][4];
#pragma unroll
        for (int ks = 0; ks < 3; ks++) {
            u32 addr = smem_u32(&Ws[(m0 + (lane & 15)) * 56 + ks * 16 + (lane >> 4) * 8]);
            asm volatile("ldmatrix.sync.aligned.m8n8.x4.shared.b16 {%0,%1,%2,%3}, [%4];"
                         : "=r"(a[0][0]), "=r"(a[0][1]), "=r"(a[0][2]), "=r"(a[0][3])
                         : "r"(addr));
            a[ks][0] = a[0][0]; a[ks][1] = a[0][1]; a[ks][2] = a[0][2]; a[ks][3] = a[0][3];
            // NOTE: rewritten below properly
        }
        // (the loop above must load into a[ks]; redo correctly)
#pragma unroll
        for (int ks = 0; ks < 3; ks++) {
            u32 addr = smem_u32(&Ws[(m0 + (lane & 15)) * 56 + ks * 16 + (lane >> 4) * 8]);
            asm volatile("ldmatrix.sync.aligned.m8n8.x4.shared.b16 {%0,%1,%2,%3}, [%4];"
                         : "=r"(a[ks][0]), "=r"(a[ks][1]), "=r"(a[ks][2]), "=r"(a[ks][3])
                         : "r"(addr));
        }

        // HMMA over this warp's n-tiles -> Qb
        for (int n = warp; n < NT; n += 9) {
            float c0 = 0.f, c1 = 0.f, c2 = 0.f, c3 = 0.f;
#pragma unroll
            for (int ks = 0; ks < 3; ks++) {
                u32 b0, b1;
                u32 baddr = smem_u32(&Xs[(ks * 16 + (lane & 15)) * XPITCH + n * 8]);
                asm volatile("ldmatrix.sync.aligned.m8n8.x2.trans.shared.b16 {%0,%1}, [%2];"
                             : "=r"(b0), "=r"(b1) : "r"(baddr));
                asm volatile("mma.sync.aligned.m16n8k16.row.col.f32.f16.f16.f32 "
                             "{%0,%1,%2,%3}, {%4,%5,%6,%7}, {%8,%9}, {%0,%1,%2,%3};"
                             : "+f"(c0), "+f"(c1), "+f"(c2), "+f"(c3)
                             : "r"(a[ks][0]), "r"(a[ks][1]), "r"(a[ks][2]), "r"(a[ks][3]),
                               "r"(b0), "r"(b1));
            }
            *(__half2*)&Qb[g       * XPITCH + n * 8 + 2 * t] = __floats2half2_rn(c0, c1);
            *(__half2*)&Qb[(g + 8) * XPITCH + n * 8 + 2 * t] = __floats2half2_rn(c2, c3);
        }
        __syncthreads();

        // depthwise 3x3 from Qb -> g_dw (16 ch x 4 rows x 64 half2)
        for (int i = tid; i < 4096; i += 288) {
            int ch = i >> 8, r = (i >> 6) & 3, p2 = i & 63;
            int j0 = p2 * 2;
            const __half* qb = Qb + ch * XPITCH + r * SEG + j0;
            float2 r0a = __half22float2(*(const __half2*)(qb));
            float2 r0b = __half22float2(*(const __half2*)(qb + 2));
            float2 r1a = __half22float2(*(const __half2*)(qb + SEG));
            float2 r1b = __half22float2(*(const __half2*)(qb + SEG + 2));
            float2 r2a = __half22float2(*(const __half2*)(qb + 2 * SEG));
            float2 r2b = __half22float2(*(const __half2*)(qb + 2 * SEG + 2));
            const float* wr = dww + ch * 9;
            float acc0 = wr[0]*r0a.x + wr[1]*r0a.y + wr[2]*r0b.x
                       + wr[3]*r1a.x + wr[4]*r1a.y + wr[5]*r1b.x
                       + wr[6]*r2a.x + wr[7]*r2a.y + wr[8]*r2b.x;
            float acc1 = wr[0]*r0a.y + wr[1]*r0b.x + wr[2]*r0b.y
                       + wr[3]*r1a.y + wr[4]*r1b.x + wr[5]*r1b.y
                       + wr[6]*r2a.y + wr[7]*r2b.x + wr[8]*r2b.y;
            __half* op = g_dw + ((size_t)b * C3 + chunk * 16 + ch) * NPIX
                       + (y0 + r) * WW + x0 + j0;
            *(__half2*)op = __floats2half2_rn(acc0, acc1);
        }
        __syncthreads();
    }
}

// ============================================================
// K3: Gram via mma (unchanged from R12 WIN).
// ============================================================
__global__ void __launch_bounds__(192) k_gram() {
    __shared__ __half Qs[C][136];
    __shared__ __half Ks[C][136];
    const int tid  = threadIdx.x;
    const int warp = tid >> 5, lane = tid & 31;
    const int b    = blockIdx.x >> 6;
    const int px0  = (blockIdx.x & 63) << 10;

    const __half* Q = g_dw + (size_t)b * C3 * NPIX;
    const __half* K = Q + (size_t)C * NPIX;

    const int m0     = (warp >> 1) * 16;
    const int n0base = (warp & 1) * 24;
    float c[3][4] = {{0.f}};
    float sq = 0.f;
    const int nch = tid % 96, npart = tid / 96;

#pragma unroll 1
    for (int chk = 0; chk < 8; chk++) {
        const int tb = px0 + chk * 128;
        __syncthreads();
        for (int i = tid; i < C * 16; i += 192) {
            int k = i >> 4, q = i & 15;
            *(uint4*)&Qs[k][q * 8] = *(const uint4*)(Q + (size_t)k * NPIX + tb + q * 8);
            *(uint4*)&Ks[k][q * 8] = *(const uint4*)(K + (size_t)k * NPIX + tb + q * 8);
        }
        __syncthreads();

        {
            const __half2* r2 = (const __half2*)(((nch < C) ? Qs[nch] : Ks[nch - C]) + npart * 64);
#pragma unroll
            for (int j = 0; j < 32; j++) {
                float2 f = __half22float2(r2[j]);
                sq += f.x * f.x + f.y * f.y;
            }
        }

#pragma unroll
        for (int ks = 0; ks < 8; ks++) {
            u32 a0r, a1r, a2r, a3r;
            u32 aaddr = smem_u32(&Qs[m0 + (lane & 15)][ks * 16 + (lane >> 4) * 8]);
            asm volatile("ldmatrix.sync.aligned.m8n8.x4.shared.b16 {%0,%1,%2,%3}, [%4];"
                         : "=r"(a0r), "=r"(a1r), "=r"(a2r), "=r"(a3r) : "r"(aaddr));
#pragma unroll
            for (int j = 0; j < 3; j++) {
                const int n0 = n0base + j * 8;
                u32 b0, b1;
                u32 baddr = smem_u32(&Ks[n0 + (lane & 7)][ks * 16 + ((lane >> 3) & 1) * 8]);
                asm volatile("ldmatrix.sync.aligned.m8n8.x2.shared.b16 {%0,%1}, [%2];"
                             : "=r"(b0), "=r"(b1) : "r"(baddr));
                asm volatile("mma.sync.aligned.m16n8k16.row.col.f32.f16.f16.f32 "
                             "{%0,%1,%2,%3}, {%4,%5,%6,%7}, {%8,%9}, {%0,%1,%2,%3};"
                             : "+f"(c[j][0]), "+f"(c[j][1]), "+f"(c[j][2]), "+f"(c[j][3])
                             : "r"(a0r), "r"(a1r), "r"(a2r), "r"(a3r), "r"(b0), "r"(b1));
            }
        }
    }

    float* gbase = g_small + b * (C * C + 2 * C);
    const int g = lane >> 2, t = lane & 3;
#pragma unroll
    for (int j = 0; j < 3; j++) {
        const int n0 = n0base + j * 8;
        atomicAdd(&gbase[(m0 + g)     * C + n0 + 2 * t],     c[j][0]);
        atomicAdd(&gbase[(m0 + g)     * C + n0 + 2 * t + 1], c[j][1]);
        atomicAdd(&gbase[(m0 + g + 8) * C + n0 + 2 * t],     c[j][2]);
        atomicAdd(&gbase[(m0 + g + 8) * C + n0 + 2 * t + 1], c[j][3]);
    }
    atomicAdd(&gbase[C * C + nch], sq);
}

// ============================================================
// K4: softmax + M = proj @ attn (unchanged).
// ============================================================
__global__ __launch_bounds__(256) void k_attn(const float* __restrict__ proj,
                                              const float* __restrict__ temp) {
    const int b = blockIdx.x;
    const int tid = threadIdx.x;
    const int warp = tid >> 5, lane = tid & 31;
    __shared__ float A[C][C + 1];
    __shared__ float P[C * C];
    __shared__ float qn[C], kn[C];
    const float* gbase = g_small + b * (C * C + 2 * C);
    const float T = temp[0];

    for (int i = tid; i < C * C; i += 256) P[i] = proj[i];
    if (tid < C)          qn[tid]     = fmaxf(sqrtf(gbase[C * C + tid]), 1e-12f);
    else if (tid < 2 * C) kn[tid - C] = fmaxf(sqrtf(gbase[C * C + tid]), 1e-12f);
    __syncthreads();

    for (int i = tid; i < C * C; i += 256) {
        int r = i / C, d = i % C;
        A[r][d] = gbase[i] * T / (qn[r] * kn[d]);
    }
    __syncthreads();

    for (int r = warp; r < C; r += 8) {
        float v0 = A[r][lane];
        float v1 = (lane + 32 < C) ? A[r][lane + 32] : -1e30f;
        float mx = fmaxf(v0, v1);
#pragma unroll
        for (int o = 16; o > 0; o >>= 1) mx = fmaxf(mx, __shfl_xor_sync(~0u, mx, o));
        float e0 = expf(v0 - mx);
        float e1 = (lane + 32 < C) ? expf(v1 - mx) : 0.f;
        float s = e0 + e1;
#pragma unroll
        for (int o = 16; o > 0; o >>= 1) s += __shfl_xor_sync(~0u, s, o);
        float inv = 1.f / s;
        A[r][lane] = e0 * inv;
        if (lane + 32 < C) A[r][lane + 32] = e1 * inv;
    }
    __syncthreads();

    float* Mb = g_M + b * C * C;
    for (int oc = warp; oc < C; oc += 8) {
        float acc0 = 0.f, acc1 = 0.f;
#pragma unroll 8
        for (int cc = 0; cc < C; cc++) {
            float p = P[oc * C + cc];
            acc0 += p * A[cc][lane];
            acc1 += p * A[cc][(lane & 15) + 32];
        }
        Mb[oc * C + lane] = acc0;
        if (lane < 16) Mb[oc * C + 32 + lane] = acc1;
    }
}

// ============================================================
// K5: out = M @ V via mma (unchanged from R12 WIN).
// ============================================================
__global__ void __launch_bounds__(192) k_out(float* __restrict__ out) {
    __shared__ __half Ms[C][56];
    __shared__ __half Vs[C][136];
    const int tid  = threadIdx.x;
    const int warp = tid >> 5, lane = tid & 31;
    const int b    = blockIdx.x >> 9;
    const int px0  = (blockIdx.x & 511) << 7;

    const float* Mb = g_M + b * C * C;
    for (int i = tid; i < C * C; i += 192)
        Ms[i / C][i % C] = __float2half_rn(Mb[i]);
    const __half* vb = g_dw + (size_t)b * C3 * NPIX + (size_t)(2 * C) * NPIX + px0;
    for (int i = tid; i < C * 16; i += 192) {
        int k = i >> 4, q = i & 15;
        *(uint4*)&Vs[k][q * 8] = *(const uint4*)(vb + (size_t)k * NPIX + q * 8);
    }
    __syncthreads();

    const int m0 = (warp >> 1) * 16;
    u32 a[3][4];
#pragma unroll
    for (int ks = 0; ks < 3; ks++) {
        u32 addr = smem_u32(&Ms[m0 + (lane & 15)][ks * 16 + (lane >> 4) * 8]);
        asm volatile("ldmatrix.sync.aligned.m8n8.x4.shared.b16 {%0,%1,%2,%3}, [%4];"
                     : "=r"(a[ks][0]), "=r"(a[ks][1]), "=r"(a[ks][2]), "=r"(a[ks][3])
                     : "r"(addr));
    }

    float* ob = out + (size_t)b * C * NPIX + px0;
    const int g = lane >> 2, t = lane & 3;
#pragma unroll 4
    for (int j = 0; j < 8; j++) {
        const int n = (warp & 1) * 8 + j;
        float c0 = 0.f, c1 = 0.f, c2 = 0.f, c3 = 0.f;
#pragma unroll
        for (int ks = 0; ks < 3; ks++) {
            u32 b0, b1;
            u32 baddr = smem_u32(&Vs[ks * 16 + (lane & 15)][n * 8]);
            asm volatile("ldmatrix.sync.aligned.m8n8.x2.trans.shared.b16 {%0,%1}, [%2];"
                         : "=r"(b0), "=r"(b1) : "r"(baddr));
            asm volatile("mma.sync.aligned.m16n8k16.row.col.f32.f16.f16.f32 "
                         "{%0,%1,%2,%3}, {%4,%5,%6,%7}, {%8,%9}, {%0,%1,%2,%3};"
                         : "+f"(c0), "+f"(c1), "+f"(c2), "+f"(c3)
                         : "r"(a[ks][0]), "r"(a[ks][1]), "r"(a[ks][2]), "r"(a[ks][3]),
                           "r"(b0), "r"(b1));
        }
        *(float2*)(ob + (size_t)(m0 + g)     * NPIX + n * 8 + 2 * t) = make_float2(c0, c1);
        *(float2*)(ob + (size_t)(m0 + g + 8) * NPIX + n * 8 + 2 * t) = make_float2(c2, c3);
    }
}

// ============================================================
extern "C" void kernel_launch(void* const* d_in, const int* in_sizes, int n_in,
                              void* d_out, int out_size) {
    const float* x      = (const float*)d_in[0];
    const float* qkv_w  = (const float*)d_in[1];
    const float* dw_w   = (const float*)d_in[2];
    const float* proj_w = (const float*)d_in[3];
    const float* temp   = (const float*)d_in[4];

    const int fused_smem = (48 * XPITCH + 16 * XPITCH + 144 * 56) * 2 + 144 * 4;
    cudaFuncSetAttribute(k_fused, cudaFuncAttributeMaxDynamicSharedMemorySize, fused_smem);

    void* smallp = nullptr;
    cudaGetSymbolAddress(&smallp, g_small);
    cudaMemsetAsync(smallp, 0, sizeof(float) * Bc * (C * C + 2 * C));

    k_fused<<<Bc * 128, 288, fused_smem>>>(x, qkv_w, dw_w);
    k_gram <<<Bc * 64,  192>>>();
    k_attn <<<Bc,       256>>>(proj_w, temp);
    k_out  <<<Bc * 512, 192>>>((float*)d_out);
}

// round 14
// speedup vs baseline: 1.4700x; 1.4700x over previous
#include <cuda_runtime.h>
#include <cuda_fp16.h>
#include <stdint.h>
#include <math.h>

#define Bc   4
#define C    48
#define C3   144
#define HH   256
#define WW   256
#define NPIX 65536   // HH*WW

typedef unsigned long long u64;
typedef unsigned int u32;

__device__ __forceinline__ u32 smem_u32(const void* p) {
    return (u32)__cvta_generic_to_shared(p);
}

// ---- scratch (device globals: no allocation allowed) ----
__device__ __half g_qkv[(size_t)Bc * C3 * NPIX];
__device__ __half g_dw [(size_t)Bc * C3 * NPIX];
__device__ float  g_small[Bc * (C * C + 2 * C)];
__device__ float  g_M[Bc * C * C];
__device__ int    g_cnt[Bc];

// ============================================================
// K1: qkv 1x1 conv via mma.m16n8k16 (R12 WIN, unchanged).
// ============================================================
__global__ void __launch_bounds__(288) k_qkv(const float* __restrict__ x,
                                             const float* __restrict__ w) {
    __shared__ __half Ws[C3][56];    // rows 112B = 7*16B (conflict-free)
    __shared__ __half Xs[C][136];    // rows 272B = 17*16B
    const int tid  = threadIdx.x;
    const int warp = tid >> 5, lane = tid & 31;
    const int b    = blockIdx.x >> 9;
    const int px0  = (blockIdx.x & 511) << 7;

    for (int i = tid; i < C3 * C; i += 288) {
        int m = i / C, k = i % C;
        Ws[m][k] = __float2half_rn(w[i]);
    }
    const float* xb = x + (size_t)b * C * NPIX + px0;
    for (int i = tid; i < C * 32; i += 288) {
        int k = i >> 5, q = i & 31;
        float4 v = *(const float4*)(xb + (size_t)k * NPIX + (q << 2));
        *(__half2*)&Xs[k][q * 4]     = __floats2half2_rn(v.x, v.y);
        *(__half2*)&Xs[k][q * 4 + 2] = __floats2half2_rn(v.z, v.w);
    }
    __syncthreads();

    const int m0 = warp * 16;
    u32 a[3][4];
#pragma unroll
    for (int ks = 0; ks < 3; ks++) {
        u32 addr = smem_u32(&Ws[m0 + (lane & 15)][(lane >> 4) * 8 + ks * 16]);
        asm volatile("ldmatrix.sync.aligned.m8n8.x4.shared.b16 {%0,%1,%2,%3}, [%4];"
                     : "=r"(a[ks][0]), "=r"(a[ks][1]), "=r"(a[ks][2]), "=r"(a[ks][3])
                     : "r"(addr));
    }

    __half* ob = g_qkv + (size_t)b * C3 * NPIX + px0;
    const int g = lane >> 2, t = lane & 3;
#pragma unroll 4
    for (int n = 0; n < 16; n++) {
        float c0 = 0.f, c1 = 0.f, c2 = 0.f, c3 = 0.f;
#pragma unroll
        for (int ks = 0; ks < 3; ks++) {
            u32 b0, b1;
            u32 baddr = smem_u32(&Xs[ks * 16 + (lane & 15)][n * 8]);
            asm volatile("ldmatrix.sync.aligned.m8n8.x2.trans.shared.b16 {%0,%1}, [%2];"
                         : "=r"(b0), "=r"(b1) : "r"(baddr));
            asm volatile("mma.sync.aligned.m16n8k16.row.col.f32.f16.f16.f32 "
                         "{%0,%1,%2,%3}, {%4,%5,%6,%7}, {%8,%9}, {%0,%1,%2,%3};"
                         : "+f"(c0), "+f"(c1), "+f"(c2), "+f"(c3)
                         : "r"(a[ks][0]), "r"(a[ks][1]), "r"(a[ks][2]), "r"(a[ks][3]),
                           "r"(b0), "r"(b1));
        }
        *(__half2*)(ob + (size_t)(m0 + g)     * NPIX + n * 8 + 2 * t) = __floats2half2_rn(c0, c1);
        *(__half2*)(ob + (size_t)(m0 + g + 8) * NPIX + n * 8 + 2 * t) = __floats2half2_rn(c2, c3);
    }
}

// ============================================================
// K2: depthwise 3x3, pad 1 (unchanged).
// ============================================================
#define DWROWS 8
__global__ __launch_bounds__(256) void k_dw(const float* __restrict__ w) {
    const int tilesY = HH / DWROWS;
    const int ytile = blockIdx.x & (tilesY - 1);
    const int ch    = (blockIdx.x / tilesY) % C3;
    const int b     = blockIdx.x / (tilesY * C3);
    const int tid   = threadIdx.x;

    const __half* in  = g_qkv + ((size_t)b * C3 + ch) * NPIX;
    __half*       out = g_dw  + ((size_t)b * C3 + ch) * NPIX;

    __shared__ float rows[DWROWS + 2][WW];
    const int y0 = ytile * DWROWS;
    for (int i = tid; i < (DWROWS + 2) * (WW / 2); i += 256) {
        int r = i / (WW / 2), c2 = i % (WW / 2);
        int y = y0 - 1 + r;
        float2 v = make_float2(0.f, 0.f);
        if (y >= 0 && y < HH)
            v = __half22float2(*(const __half2*)(in + y * WW + 2 * c2));
        rows[r][2 * c2] = v.x; rows[r][2 * c2 + 1] = v.y;
    }
    __syncthreads();

    const float w00 = w[ch*9+0], w01 = w[ch*9+1], w02 = w[ch*9+2];
    const float w10 = w[ch*9+3], w11 = w[ch*9+4], w12 = w[ch*9+5];
    const float w20 = w[ch*9+6], w21 = w[ch*9+7], w22 = w[ch*9+8];

    const int half = tid >> 7;
    const int c2   = tid & 127;
    const int col0 = 2 * c2, col1 = col0 + 1;
    const float lm = (c2 > 0) ? 1.f : 0.f;
    const float rm = (c2 < 127) ? 1.f : 0.f;
    const int xl = max(col0 - 1, 0), xr = min(col1 + 1, WW - 1);

#pragma unroll
    for (int rr = 0; rr < DWROWS / 2; rr++) {
        const int r = 2 * rr + half;
        const float* r0 = rows[r], *r1 = rows[r + 1], *r2 = rows[r + 2];
        float a0 = r0[xl] * lm, b0 = r0[col0], c0v = r0[col1], d0 = r0[xr] * rm;
        float a1 = r1[xl] * lm, b1 = r1[col0], c1v = r1[col1], d1 = r1[xr] * rm;
        float a2 = r2[xl] * lm, b2 = r2[col0], c2v = r2[col1], d2 = r2[xr] * rm;
        float acc0 = w00*a0 + w01*b0 + w02*c0v + w10*a1 + w11*b1 + w12*c1v + w20*a2 + w21*b2 + w22*c2v;
        float acc1 = w00*b0 + w01*c0v + w02*d0 + w10*b1 + w11*c1v + w12*d1 + w20*b2 + w21*c2v + w22*d2;
        *(__half2*)(out + (y0 + r) * WW + col0) = __floats2half2_rn(acc0, acc1);
    }
}

// ============================================================
// K3: Gram via mma (R12 WIN) + fused attn epilogue in the
// last-finishing block per batch (atomic counter), reusing smem.
// ============================================================
__global__ void __launch_bounds__(192) k_gram(const float* __restrict__ proj,
                                              const float* __restrict__ temp) {
    __shared__ __half Qs[C][136];
    __shared__ __half Ks[C][136];
    __shared__ int isLast;
    const int tid  = threadIdx.x;
    const int warp = tid >> 5, lane = tid & 31;
    const int b    = blockIdx.x >> 6;
    const int px0  = (blockIdx.x & 63) << 10;

    const __half* Q = g_dw + (size_t)b * C3 * NPIX;
    const __half* K = Q + (size_t)C * NPIX;

    const int m0     = (warp >> 1) * 16;
    const int n0base = (warp & 1) * 24;
    float c[3][4] = {{0.f}};
    float sq = 0.f;
    const int nch = tid % 96, npart = tid / 96;

#pragma unroll 1
    for (int chk = 0; chk < 8; chk++) {
        const int tb = px0 + chk * 128;
        __syncthreads();
        for (int i = tid; i < C * 16; i += 192) {
            int k = i >> 4, q = i & 15;
            *(uint4*)&Qs[k][q * 8] = *(const uint4*)(Q + (size_t)k * NPIX + tb + q * 8);
            *(uint4*)&Ks[k][q * 8] = *(const uint4*)(K + (size_t)k * NPIX + tb + q * 8);
        }
        __syncthreads();

        {
            const __half2* r2 = (const __half2*)(((nch < C) ? Qs[nch] : Ks[nch - C]) + npart * 64);
#pragma unroll
            for (int j = 0; j < 32; j++) {
                float2 f = __half22float2(r2[j]);
                sq += f.x * f.x + f.y * f.y;
            }
        }

#pragma unroll
        for (int ks = 0; ks < 8; ks++) {
            u32 a0r, a1r, a2r, a3r;
            u32 aaddr = smem_u32(&Qs[m0 + (lane & 15)][ks * 16 + (lane >> 4) * 8]);
            asm volatile("ldmatrix.sync.aligned.m8n8.x4.shared.b16 {%0,%1,%2,%3}, [%4];"
                         : "=r"(a0r), "=r"(a1r), "=r"(a2r), "=r"(a3r) : "r"(aaddr));
#pragma unroll
            for (int j = 0; j < 3; j++) {
                const int n0 = n0base + j * 8;
                u32 b0, b1;
                u32 baddr = smem_u32(&Ks[n0 + (lane & 7)][ks * 16 + ((lane >> 3) & 1) * 8]);
                asm volatile("ldmatrix.sync.aligned.m8n8.x2.shared.b16 {%0,%1}, [%2];"
                             : "=r"(b0), "=r"(b1) : "r"(baddr));
                asm volatile("mma.sync.aligned.m16n8k16.row.col.f32.f16.f16.f32 "
                             "{%0,%1,%2,%3}, {%4,%5,%6,%7}, {%8,%9}, {%0,%1,%2,%3};"
                             : "+f"(c[j][0]), "+f"(c[j][1]), "+f"(c[j][2]), "+f"(c[j][3])
                             : "r"(a0r), "r"(a1r), "r"(a2r), "r"(a3r), "r"(b0), "r"(b1));
            }
        }
    }

    float* gbase = g_small + b * (C * C + 2 * C);
    const int g = lane >> 2, t = lane & 3;
#pragma unroll
    for (int j = 0; j < 3; j++) {
        const int n0 = n0base + j * 8;
        atomicAdd(&gbase[(m0 + g)     * C + n0 + 2 * t],     c[j][0]);
        atomicAdd(&gbase[(m0 + g)     * C + n0 + 2 * t + 1], c[j][1]);
        atomicAdd(&gbase[(m0 + g + 8) * C + n0 + 2 * t],     c[j][2]);
        atomicAdd(&gbase[(m0 + g + 8) * C + n0 + 2 * t + 1], c[j][3]);
    }
    atomicAdd(&gbase[C * C + nch], sq);

    // ---- last block of this batch runs the attn tail ----
    __threadfence();
    if (tid == 0) isLast = (atomicAdd(&g_cnt[b], 1) == 63) ? 1 : 0;
    __syncthreads();
    if (!isLast) return;

    // reuse smem: A over Qs, P/qn/kn over Ks
    float (*A)[C + 1] = (float(*)[C + 1])Qs;   // 9.4 KB <= 13 KB
    float* P  = (float*)Ks;                    // 9.2 KB
    float* qn = P + C * C;
    float* kn = qn + C;
    const volatile float* gb = gbase;
    const float T = temp[0];

    for (int i = tid; i < C * C; i += 192) P[i] = proj[i];
    if (tid < C)          qn[tid]     = fmaxf(sqrtf(gb[C * C + tid]), 1e-12f);
    else if (tid < 2 * C) kn[tid - C] = fmaxf(sqrtf(gb[C * C + tid]), 1e-12f);
    __syncthreads();

    for (int i = tid; i < C * C; i += 192) {
        int r = i / C, d = i % C;
        A[r][d] = gb[i] * T / (qn[r] * kn[d]);
    }
    __syncthreads();

    for (int r = warp; r < C; r += 6) {
        float v0 = A[r][lane];
        float v1 = (lane + 32 < C) ? A[r][lane + 32] : -1e30f;
        float mx = fmaxf(v0, v1);
#pragma unroll
        for (int o = 16; o > 0; o >>= 1) mx = fmaxf(mx, __shfl_xor_sync(~0u, mx, o));
        float e0 = expf(v0 - mx);
        float e1 = (lane + 32 < C) ? expf(v1 - mx) : 0.f;
        float s = e0 + e1;
#pragma unroll
        for (int o = 16; o > 0; o >>= 1) s += __shfl_xor_sync(~0u, s, o);
        float inv = 1.f / s;
        A[r][lane] = e0 * inv;
        if (lane + 32 < C) A[r][lane + 32] = e1 * inv;
    }
    __syncthreads();

    float* Mb = g_M + b * C * C;
    for (int oc = warp; oc < C; oc += 6) {
        float acc0 = 0.f, acc1 = 0.f;
#pragma unroll 8
        for (int cc = 0; cc < C; cc++) {
            float p = P[oc * C + cc];
            acc0 += p * A[cc][lane];
            acc1 += p * A[cc][(lane & 15) + 32];
        }
        Mb[oc * C + lane] = acc0;
        if (lane < 16) Mb[oc * C + 32 + lane] = acc1;
    }
}

// ============================================================
// K5: out = M @ V via mma (R12 WIN, unchanged).
// ============================================================
__global__ void __launch_bounds__(192) k_out(float* __restrict__ out) {
    __shared__ __half Ms[C][56];
    __shared__ __half Vs[C][136];
    const int tid  = threadIdx.x;
    const int warp = tid >> 5, lane = tid & 31;
    const int b    = blockIdx.x >> 9;
    const int px0  = (blockIdx.x & 511) << 7;

    const float* Mb = g_M + b * C * C;
    for (int i = tid; i < C * C; i += 192)
        Ms[i / C][i % C] = __float2half_rn(Mb[i]);
    const __half* vb = g_dw + (size_t)b * C3 * NPIX + (size_t)(2 * C) * NPIX + px0;
    for (int i = tid; i < C * 16; i += 192) {
        int k = i >> 4, q = i & 15;
        *(uint4*)&Vs[k][q * 8] = *(const uint4*)(vb + (size_t)k * NPIX + q * 8);
    }
    __syncthreads();

    const int m0 = (warp >> 1) * 16;
    u32 a[3][4];
#pragma unroll
    for (int ks = 0; ks < 3; ks++) {
        u32 addr = smem_u32(&Ms[m0 + (lane & 15)][ks * 16 + (lane >> 4) * 8]);
        asm volatile("ldmatrix.sync.aligned.m8n8.x4.shared.b16 {%0,%1,%2,%3}, [%4];"
                     : "=r"(a[ks][0]), "=r"(a[ks][1]), "=r"(a[ks][2]), "=r"(a[ks][3])
                     : "r"(addr));
    }

    float* ob = out + (size_t)b * C * NPIX + px0;
    const int g = lane >> 2, t = lane & 3;
#pragma unroll 4
    for (int j = 0; j < 8; j++) {
        const int n = (warp & 1) * 8 + j;
        float c0 = 0.f, c1 = 0.f, c2 = 0.f, c3 = 0.f;
#pragma unroll
        for (int ks = 0; ks < 3; ks++) {
            u32 b0, b1;
            u32 baddr = smem_u32(&Vs[ks * 16 + (lane & 15)][n * 8]);
            asm volatile("ldmatrix.sync.aligned.m8n8.x2.trans.shared.b16 {%0,%1}, [%2];"
                         : "=r"(b0), "=r"(b1) : "r"(baddr));
            asm volatile("mma.sync.aligned.m16n8k16.row.col.f32.f16.f16.f32 "
                         "{%0,%1,%2,%3}, {%4,%5,%6,%7}, {%8,%9}, {%0,%1,%2,%3};"
                         : "+f"(c0), "+f"(c1), "+f"(c2), "+f"(c3)
                         : "r"(a[ks][0]), "r"(a[ks][1]), "r"(a[ks][2]), "r"(a[ks][3]),
                           "r"(b0), "r"(b1));
        }
        *(float2*)(ob + (size_t)(m0 + g)     * NPIX + n * 8 + 2 * t) = make_float2(c0, c1);
        *(float2*)(ob + (size_t)(m0 + g + 8) * NPIX + n * 8 + 2 * t) = make_float2(c2, c3);
    }
}

// ============================================================
extern "C" void kernel_launch(void* const* d_in, const int* in_sizes, int n_in,
                              void* d_out, int out_size) {
    const float* x      = (const float*)d_in[0];
    const float* qkv_w  = (const float*)d_in[1];
    const float* dw_w   = (const float*)d_in[2];
    const float* proj_w = (const float*)d_in[3];
    const float* temp   = (const float*)d_in[4];

    void* smallp = nullptr;
    cudaGetSymbolAddress(&smallp, g_small);
    cudaMemsetAsync(smallp, 0, sizeof(float) * Bc * (C * C + 2 * C));
    void* cntp = nullptr;
    cudaGetSymbolAddress(&cntp, g_cnt);
    cudaMemsetAsync(cntp, 0, sizeof(int) * Bc);

    k_qkv <<<Bc * 512,                288>>>(x, qkv_w);
    k_dw  <<<Bc * C3 * (HH / DWROWS), 256>>>(dw_w);
    k_gram<<<Bc * 64,                 192>>>(proj_w, temp);
    k_out <<<Bc * 512,                192>>>((float*)d_out);
}

// round 15
// speedup vs baseline: 1.5589x; 1.0605x over previous
#include <cuda_runtime.h>
#include <cuda_fp16.h>
#include <stdint.h>
#include <math.h>

#define Bc   4
#define C    48
#define C3   144
#define HH   256
#define WW   256
#define NPIX 65536   // HH*WW

typedef unsigned long long u64;
typedef unsigned int u32;

__device__ __forceinline__ u32 smem_u32(const void* p) {
    return (u32)__cvta_generic_to_shared(p);
}

// ---- scratch (device globals: no allocation allowed) ----
__device__ __half g_qkv[(size_t)Bc * C3 * NPIX];
__device__ __half g_dw [(size_t)Bc * C3 * NPIX];
__device__ float  g_small[Bc * (C * C + 2 * C)];
__device__ float  g_M[Bc * C * C];
__device__ int    g_cnt[Bc];

// ============================================================
// K1: qkv 1x1 conv via mma.m16n8k16. B loads use ldmatrix.x4.trans
// (2 n-tiles per instruction: lanes 16-31 address column n+1).
// ============================================================
__global__ void __launch_bounds__(288) k_qkv(const float* __restrict__ x,
                                             const float* __restrict__ w) {
    __shared__ __half Ws[C3][56];    // rows 112B = 7*16B (conflict-free)
    __shared__ __half Xs[C][136];    // rows 272B = 17*16B
    const int tid  = threadIdx.x;
    const int warp = tid >> 5, lane = tid & 31;
    const int b    = blockIdx.x >> 9;
    const int px0  = (blockIdx.x & 511) << 7;

    for (int i = tid; i < C3 * C; i += 288) {
        int m = i / C, k = i % C;
        Ws[m][k] = __float2half_rn(w[i]);
    }
    const float* xb = x + (size_t)b * C * NPIX + px0;
    for (int i = tid; i < C * 32; i += 288) {
        int k = i >> 5, q = i & 31;
        float4 v = *(const float4*)(xb + (size_t)k * NPIX + (q << 2));
        *(__half2*)&Xs[k][q * 4]     = __floats2half2_rn(v.x, v.y);
        *(__half2*)&Xs[k][q * 4 + 2] = __floats2half2_rn(v.z, v.w);
    }
    __syncthreads();

    const int m0 = warp * 16;
    u32 a[3][4];
#pragma unroll
    for (int ks = 0; ks < 3; ks++) {
        u32 addr = smem_u32(&Ws[m0 + (lane & 15)][(lane >> 4) * 8 + ks * 16]);
        asm volatile("ldmatrix.sync.aligned.m8n8.x4.shared.b16 {%0,%1,%2,%3}, [%4];"
                     : "=r"(a[ks][0]), "=r"(a[ks][1]), "=r"(a[ks][2]), "=r"(a[ks][3])
                     : "r"(addr));
    }

    __half* ob = g_qkv + (size_t)b * C3 * NPIX + px0;
    const int g = lane >> 2, t = lane & 3;
#pragma unroll 2
    for (int n = 0; n < 16; n += 2) {
        float c0[4] = {0.f, 0.f, 0.f, 0.f};
        float c1[4] = {0.f, 0.f, 0.f, 0.f};
#pragma unroll
        for (int ks = 0; ks < 3; ks++) {
            u32 b0, b1, b2, b3;
            u32 baddr = smem_u32(&Xs[ks * 16 + (lane & 15)][(n + (lane >> 4)) * 8]);
            asm volatile("ldmatrix.sync.aligned.m8n8.x4.trans.shared.b16 {%0,%1,%2,%3}, [%4];"
                         : "=r"(b0), "=r"(b1), "=r"(b2), "=r"(b3) : "r"(baddr));
            asm volatile("mma.sync.aligned.m16n8k16.row.col.f32.f16.f16.f32 "
                         "{%0,%1,%2,%3}, {%4,%5,%6,%7}, {%8,%9}, {%0,%1,%2,%3};"
                         : "+f"(c0[0]), "+f"(c0[1]), "+f"(c0[2]), "+f"(c0[3])
                         : "r"(a[ks][0]), "r"(a[ks][1]), "r"(a[ks][2]), "r"(a[ks][3]),
                           "r"(b0), "r"(b1));
            asm volatile("mma.sync.aligned.m16n8k16.row.col.f32.f16.f16.f32 "
                         "{%0,%1,%2,%3}, {%4,%5,%6,%7}, {%8,%9}, {%0,%1,%2,%3};"
                         : "+f"(c1[0]), "+f"(c1[1]), "+f"(c1[2]), "+f"(c1[3])
                         : "r"(a[ks][0]), "r"(a[ks][1]), "r"(a[ks][2]), "r"(a[ks][3]),
                           "r"(b2), "r"(b3));
        }
        *(__half2*)(ob + (size_t)(m0 + g)     * NPIX + n * 8 + 2 * t)       = __floats2half2_rn(c0[0], c0[1]);
        *(__half2*)(ob + (size_t)(m0 + g + 8) * NPIX + n * 8 + 2 * t)       = __floats2half2_rn(c0[2], c0[3]);
        *(__half2*)(ob + (size_t)(m0 + g)     * NPIX + (n + 1) * 8 + 2 * t) = __floats2half2_rn(c1[0], c1[1]);
        *(__half2*)(ob + (size_t)(m0 + g + 8) * NPIX + (n + 1) * 8 + 2 * t) = __floats2half2_rn(c1[2], c1[3]);
    }
}

// ============================================================
// K2: depthwise 3x3, pad 1 (unchanged).
// ============================================================
#define DWROWS 8
__global__ __launch_bounds__(256) void k_dw(const float* __restrict__ w) {
    const int tilesY = HH / DWROWS;
    const int ytile = blockIdx.x & (tilesY - 1);
    const int ch    = (blockIdx.x / tilesY) % C3;
    const int b     = blockIdx.x / (tilesY * C3);
    const int tid   = threadIdx.x;

    const __half* in  = g_qkv + ((size_t)b * C3 + ch) * NPIX;
    __half*       out = g_dw  + ((size_t)b * C3 + ch) * NPIX;

    __shared__ float rows[DWROWS + 2][WW];
    const int y0 = ytile * DWROWS;
    for (int i = tid; i < (DWROWS + 2) * (WW / 2); i += 256) {
        int r = i / (WW / 2), c2 = i % (WW / 2);
        int y = y0 - 1 + r;
        float2 v = make_float2(0.f, 0.f);
        if (y >= 0 && y < HH)
            v = __half22float2(*(const __half2*)(in + y * WW + 2 * c2));
        rows[r][2 * c2] = v.x; rows[r][2 * c2 + 1] = v.y;
    }
    __syncthreads();

    const float w00 = w[ch*9+0], w01 = w[ch*9+1], w02 = w[ch*9+2];
    const float w10 = w[ch*9+3], w11 = w[ch*9+4], w12 = w[ch*9+5];
    const float w20 = w[ch*9+6], w21 = w[ch*9+7], w22 = w[ch*9+8];

    const int half = tid >> 7;
    const int c2   = tid & 127;
    const int col0 = 2 * c2, col1 = col0 + 1;
    const float lm = (c2 > 0) ? 1.f : 0.f;
    const float rm = (c2 < 127) ? 1.f : 0.f;
    const int xl = max(col0 - 1, 0), xr = min(col1 + 1, WW - 1);

#pragma unroll
    for (int rr = 0; rr < DWROWS / 2; rr++) {
        const int r = 2 * rr + half;
        const float* r0 = rows[r], *r1 = rows[r + 1], *r2 = rows[r + 2];
        float a0 = r0[xl] * lm, b0 = r0[col0], c0v = r0[col1], d0 = r0[xr] * rm;
        float a1 = r1[xl] * lm, b1 = r1[col0], c1v = r1[col1], d1 = r1[xr] * rm;
        float a2 = r2[xl] * lm, b2 = r2[col0], c2v = r2[col1], d2 = r2[xr] * rm;
        float acc0 = w00*a0 + w01*b0 + w02*c0v + w10*a1 + w11*b1 + w12*c1v + w20*a2 + w21*b2 + w22*c2v;
        float acc1 = w00*b0 + w01*c0v + w02*d0 + w10*b1 + w11*c1v + w12*d1 + w20*b2 + w21*c2v + w22*d2;
        *(__half2*)(out + (y0 + r) * WW + col0) = __floats2half2_rn(acc0, acc1);
    }
}

// ============================================================
// K3: Gram via mma, register-prefetch double buffering + fused
// attn tail in the last-finishing block per batch.
// ============================================================
__global__ void __launch_bounds__(192) k_gram(const float* __restrict__ proj,
                                              const float* __restrict__ temp) {
    __shared__ __half Qs[C][136];
    __shared__ __half Ks[C][136];
    __shared__ int isLast;
    const int tid  = threadIdx.x;
    const int warp = tid >> 5, lane = tid & 31;
    const int b    = blockIdx.x >> 6;
    const int px0  = (blockIdx.x & 63) << 10;

    const __half* Q = g_dw + (size_t)b * C3 * NPIX;
    const __half* K = Q + (size_t)C * NPIX;

    const int m0     = (warp >> 1) * 16;
    const int n0base = (warp & 1) * 24;
    float c[3][4] = {{0.f}};
    float sq = 0.f;
    const int nch = tid % 96, npart = tid / 96;

    // stage chunk 0
    for (int i = tid; i < C * 16; i += 192) {
        int k = i >> 4, q = i & 15;
        *(uint4*)&Qs[k][q * 8] = *(const uint4*)(Q + (size_t)k * NPIX + px0 + q * 8);
        *(uint4*)&Ks[k][q * 8] = *(const uint4*)(K + (size_t)k * NPIX + px0 + q * 8);
    }
    __syncthreads();

#pragma unroll 1
    for (int chk = 0; chk < 8; chk++) {
        // prefetch next chunk into registers (4 uint4 each side)
        uint4 pq[4], pk[4];
        if (chk < 7) {
            const int tb = px0 + (chk + 1) * 128;
#pragma unroll
            for (int j = 0; j < 4; j++) {
                int i = tid + j * 192;
                int k = i >> 4, q = i & 15;
                pq[j] = *(const uint4*)(Q + (size_t)k * NPIX + tb + q * 8);
                pk[j] = *(const uint4*)(K + (size_t)k * NPIX + tb + q * 8);
            }
        }

        // norms
        {
            const __half2* r2 = (const __half2*)(((nch < C) ? Qs[nch] : Ks[nch - C]) + npart * 64);
#pragma unroll
            for (int j = 0; j < 32; j++) {
                float2 f = __half22float2(r2[j]);
                sq += f.x * f.x + f.y * f.y;
            }
        }

        // mma: 8 k-steps
#pragma unroll
        for (int ks = 0; ks < 8; ks++) {
            u32 a0r, a1r, a2r, a3r;
            u32 aaddr = smem_u32(&Qs[m0 + (lane & 15)][ks * 16 + (lane >> 4) * 8]);
            asm volatile("ldmatrix.sync.aligned.m8n8.x4.shared.b16 {%0,%1,%2,%3}, [%4];"
                         : "=r"(a0r), "=r"(a1r), "=r"(a2r), "=r"(a3r) : "r"(aaddr));
#pragma unroll
            for (int j = 0; j < 3; j++) {
                const int n0 = n0base + j * 8;
                u32 b0, b1;
                u32 baddr = smem_u32(&Ks[n0 + (lane & 7)][ks * 16 + ((lane >> 3) & 1) * 8]);
                asm volatile("ldmatrix.sync.aligned.m8n8.x2.shared.b16 {%0,%1}, [%2];"
                             : "=r"(b0), "=r"(b1) : "r"(baddr));
                asm volatile("mma.sync.aligned.m16n8k16.row.col.f32.f16.f16.f32 "
                             "{%0,%1,%2,%3}, {%4,%5,%6,%7}, {%8,%9}, {%0,%1,%2,%3};"
                             : "+f"(c[j][0]), "+f"(c[j][1]), "+f"(c[j][2]), "+f"(c[j][3])
                             : "r"(a0r), "r"(a1r), "r"(a2r), "r"(a3r), "r"(b0), "r"(b1));
            }
        }
        __syncthreads();
        if (chk < 7) {
#pragma unroll
            for (int j = 0; j < 4; j++) {
                int i = tid + j * 192;
                int k = i >> 4, q = i & 15;
                *(uint4*)&Qs[k][q * 8] = pq[j];
                *(uint4*)&Ks[k][q * 8] = pk[j];
            }
            __syncthreads();
        }
    }

    float* gbase = g_small + b * (C * C + 2 * C);
    const int g = lane >> 2, t = lane & 3;
#pragma unroll
    for (int j = 0; j < 3; j++) {
        const int n0 = n0base + j * 8;
        atomicAdd(&gbase[(m0 + g)     * C + n0 + 2 * t],     c[j][0]);
        atomicAdd(&gbase[(m0 + g)     * C + n0 + 2 * t + 1], c[j][1]);
        atomicAdd(&gbase[(m0 + g + 8) * C + n0 + 2 * t],     c[j][2]);
        atomicAdd(&gbase[(m0 + g + 8) * C + n0 + 2 * t + 1], c[j][3]);
    }
    atomicAdd(&gbase[C * C + nch], sq);

    // ---- last block of this batch runs the attn tail ----
    __threadfence();
    if (tid == 0) isLast = (atomicAdd(&g_cnt[b], 1) == 63) ? 1 : 0;
    __syncthreads();
    if (!isLast) return;

    float (*A)[C + 1] = (float(*)[C + 1])Qs;
    float* P  = (float*)Ks;
    float* qn = P + C * C;
    float* kn = qn + C;
    const volatile float* gb = gbase;
    const float T = temp[0];

    for (int i = tid; i < C * C; i += 192) P[i] = proj[i];
    if (tid < C)          qn[tid]     = fmaxf(sqrtf(gb[C * C + tid]), 1e-12f);
    else if (tid < 2 * C) kn[tid - C] = fmaxf(sqrtf(gb[C * C + tid]), 1e-12f);
    __syncthreads();

    for (int i = tid; i < C * C; i += 192) {
        int r = i / C, d = i % C;
        A[r][d] = gb[i] * T / (qn[r] * kn[d]);
    }
    __syncthreads();

    for (int r = warp; r < C; r += 6) {
        float v0 = A[r][lane];
        float v1 = (lane + 32 < C) ? A[r][lane + 32] : -1e30f;
        float mx = fmaxf(v0, v1);
#pragma unroll
        for (int o = 16; o > 0; o >>= 1) mx = fmaxf(mx, __shfl_xor_sync(~0u, mx, o));
        float e0 = expf(v0 - mx);
        float e1 = (lane + 32 < C) ? expf(v1 - mx) : 0.f;
        float s = e0 + e1;
#pragma unroll
        for (int o = 16; o > 0; o >>= 1) s += __shfl_xor_sync(~0u, s, o);
        float inv = 1.f / s;
        A[r][lane] = e0 * inv;
        if (lane + 32 < C) A[r][lane + 32] = e1 * inv;
    }
    __syncthreads();

    float* Mb = g_M + b * C * C;
    for (int oc = warp; oc < C; oc += 6) {
        float acc0 = 0.f, acc1 = 0.f;
#pragma unroll 8
        for (int cc = 0; cc < C; cc++) {
            float p = P[oc * C + cc];
            acc0 += p * A[cc][lane];
            acc1 += p * A[cc][(lane & 15) + 32];
        }
        Mb[oc * C + lane] = acc0;
        if (lane < 16) Mb[oc * C + 32 + lane] = acc1;
    }
}

// ============================================================
// K5: out = M @ V via mma, B loads with ldmatrix.x4.trans.
// ============================================================
__global__ void __launch_bounds__(192) k_out(float* __restrict__ out) {
    __shared__ __half Ms[C][56];
    __shared__ __half Vs[C][136];
    const int tid  = threadIdx.x;
    const int warp = tid >> 5, lane = tid & 31;
    const int b    = blockIdx.x >> 9;
    const int px0  = (blockIdx.x & 511) << 7;

    const float* Mb = g_M + b * C * C;
    for (int i = tid; i < C * C; i += 192)
        Ms[i / C][i % C] = __float2half_rn(Mb[i]);
    const __half* vb = g_dw + (size_t)b * C3 * NPIX + (size_t)(2 * C) * NPIX + px0;
    for (int i = tid; i < C * 16; i += 192) {
        int k = i >> 4, q = i & 15;
        *(uint4*)&Vs[k][q * 8] = *(const uint4*)(vb + (size_t)k * NPIX + q * 8);
    }
    __syncthreads();

    const int m0 = (warp >> 1) * 16;
    u32 a[3][4];
#pragma unroll
    for (int ks = 0; ks < 3; ks++) {
        u32 addr = smem_u32(&Ms[m0 + (lane & 15)][ks * 16 + (lane >> 4) * 8]);
        asm volatile("ldmatrix.sync.aligned.m8n8.x4.shared.b16 {%0,%1,%2,%3}, [%4];"
                     : "=r"(a[ks][0]), "=r"(a[ks][1]), "=r"(a[ks][2]), "=r"(a[ks][3])
                     : "r"(addr));
    }

    float* ob = out + (size_t)b * C * NPIX + px0;
    const int g = lane >> 2, t = lane & 3;
#pragma unroll 2
    for (int j = 0; j < 8; j += 2) {
        const int n = (warp & 1) * 8 + j;
        float c0[4] = {0.f, 0.f, 0.f, 0.f};
        float c1[4] = {0.f, 0.f, 0.f, 0.f};
#pragma unroll
        for (int ks = 0; ks < 3; ks++) {
            u32 b0, b1, b2, b3;
            u32 baddr = smem_u32(&Vs[ks * 16 + (lane & 15)][(n + (lane >> 4)) * 8]);
            asm volatile("ldmatrix.sync.aligned.m8n8.x4.trans.shared.b16 {%0,%1,%2,%3}, [%4];"
                         : "=r"(b0), "=r"(b1), "=r"(b2), "=r"(b3) : "r"(baddr));
            asm volatile("mma.sync.aligned.m16n8k16.row.col.f32.f16.f16.f32 "
                         "{%0,%1,%2,%3}, {%4,%5,%6,%7}, {%8,%9}, {%0,%1,%2,%3};"
                         : "+f"(c0[0]), "+f"(c0[1]), "+f"(c0[2]), "+f"(c0[3])
                         : "r"(a[ks][0]), "r"(a[ks][1]), "r"(a[ks][2]), "r"(a[ks][3]),
                           "r"(b0), "r"(b1));
            asm volatile("mma.sync.aligned.m16n8k16.row.col.f32.f16.f16.f32 "
                         "{%0,%1,%2,%3}, {%4,%5,%6,%7}, {%8,%9}, {%0,%1,%2,%3};"
                         : "+f"(c1[0]), "+f"(c1[1]), "+f"(c1[2]), "+f"(c1[3])
                         : "r"(a[ks][0]), "r"(a[ks][1]), "r"(a[ks][2]), "r"(a[ks][3]),
                           "r"(b2), "r"(b3));
        }
        *(float2*)(ob + (size_t)(m0 + g)     * NPIX + n * 8 + 2 * t)       = make_float2(c0[0], c0[1]);
        *(float2*)(ob + (size_t)(m0 + g + 8) * NPIX + n * 8 + 2 * t)       = make_float2(c0[2], c0[3]);
        *(float2*)(ob + (size_t)(m0 + g)     * NPIX + (n + 1) * 8 + 2 * t) = make_float2(c1[0], c1[1]);
        *(float2*)(ob + (size_t)(m0 + g + 8) * NPIX + (n + 1) * 8 + 2 * t) = make_float2(c1[2], c1[3]);
    }
}

// ============================================================
extern "C" void kernel_launch(void* const* d_in, const int* in_sizes, int n_in,
                              void* d_out, int out_size) {
    const float* x      = (const float*)d_in[0];
    const float* qkv_w  = (const float*)d_in[1];
    const float* dw_w   = (const float*)d_in[2];
    const float* proj_w = (const float*)d_in[3];
    const float* temp   = (const float*)d_in[4];

    void* smallp = nullptr;
    cudaGetSymbolAddress(&smallp, g_small);
    cudaMemsetAsync(smallp, 0, sizeof(float) * Bc * (C * C + 2 * C));
    void* cntp = nullptr;
    cudaGetSymbolAddress(&cntp, g_cnt);
    cudaMemsetAsync(cntp, 0, sizeof(int) * Bc);

    k_qkv <<<Bc * 512,                288>>>(x, qkv_w);
    k_dw  <<<Bc * C3 * (HH / DWROWS), 256>>>(dw_w);
    k_gram<<<Bc * 64,                 192>>>(proj_w, temp);
    k_out <<<Bc * 512,                192>>>((float*)d_out);
}

// round 16
// speedup vs baseline: 1.8933x; 1.2145x over previous
#include <cuda_runtime.h>
#include <cuda_fp16.h>
#include <stdint.h>
#include <math.h>

#define Bc   4
#define C    48
#define C3   144
#define HH   256
#define WW   256
#define NPIX 65536   // HH*WW

typedef unsigned long long u64;
typedef unsigned int u32;

__device__ __forceinline__ u32 smem_u32(const void* p) {
    return (u32)__cvta_generic_to_shared(p);
}

// ---- scratch (device globals: no allocation allowed) ----
__device__ __half g_qkv[(size_t)Bc * C3 * NPIX];
__device__ __half g_dw [(size_t)Bc * C3 * NPIX];
__device__ float  g_small[Bc * (C * C + 2 * C)];
__device__ float  g_M[Bc * C * C];
__device__ int    g_cnt[Bc];

// ============================================================
// K1: qkv 1x1 conv via mma.m16n8k16 + x4.trans B loads (R15 WIN).
// ============================================================
__global__ void __launch_bounds__(288) k_qkv(const float* __restrict__ x,
                                             const float* __restrict__ w) {
    __shared__ __half Ws[C3][56];
    __shared__ __half Xs[C][136];
    const int tid  = threadIdx.x;
    const int warp = tid >> 5, lane = tid & 31;
    const int b    = blockIdx.x >> 9;
    const int px0  = (blockIdx.x & 511) << 7;

    for (int i = tid; i < C3 * C; i += 288) {
        int m = i / C, k = i % C;
        Ws[m][k] = __float2half_rn(w[i]);
    }
    const float* xb = x + (size_t)b * C * NPIX + px0;
    for (int i = tid; i < C * 32; i += 288) {
        int k = i >> 5, q = i & 31;
        float4 v = *(const float4*)(xb + (size_t)k * NPIX + (q << 2));
        *(__half2*)&Xs[k][q * 4]     = __floats2half2_rn(v.x, v.y);
        *(__half2*)&Xs[k][q * 4 + 2] = __floats2half2_rn(v.z, v.w);
    }
    __syncthreads();

    const int m0 = warp * 16;
    u32 a[3][4];
#pragma unroll
    for (int ks = 0; ks < 3; ks++) {
        u32 addr = smem_u32(&Ws[m0 + (lane & 15)][(lane >> 4) * 8 + ks * 16]);
        asm volatile("ldmatrix.sync.aligned.m8n8.x4.shared.b16 {%0,%1,%2,%3}, [%4];"
                     : "=r"(a[ks][0]), "=r"(a[ks][1]), "=r"(a[ks][2]), "=r"(a[ks][3])
                     : "r"(addr));
    }

    __half* ob = g_qkv + (size_t)b * C3 * NPIX + px0;
    const int g = lane >> 2, t = lane & 3;
#pragma unroll 2
    for (int n = 0; n < 16; n += 2) {
        float c0[4] = {0.f, 0.f, 0.f, 0.f};
        float c1[4] = {0.f, 0.f, 0.f, 0.f};
#pragma unroll
        for (int ks = 0; ks < 3; ks++) {
            u32 b0, b1, b2, b3;
            u32 baddr = smem_u32(&Xs[ks * 16 + (lane & 15)][(n + (lane >> 4)) * 8]);
            asm volatile("ldmatrix.sync.aligned.m8n8.x4.trans.shared.b16 {%0,%1,%2,%3}, [%4];"
                         : "=r"(b0), "=r"(b1), "=r"(b2), "=r"(b3) : "r"(baddr));
            asm volatile("mma.sync.aligned.m16n8k16.row.col.f32.f16.f16.f32 "
                         "{%0,%1,%2,%3}, {%4,%5,%6,%7}, {%8,%9}, {%0,%1,%2,%3};"
                         : "+f"(c0[0]), "+f"(c0[1]), "+f"(c0[2]), "+f"(c0[3])
                         : "r"(a[ks][0]), "r"(a[ks][1]), "r"(a[ks][2]), "r"(a[ks][3]),
                           "r"(b0), "r"(b1));
            asm volatile("mma.sync.aligned.m16n8k16.row.col.f32.f16.f16.f32 "
                         "{%0,%1,%2,%3}, {%4,%5,%6,%7}, {%8,%9}, {%0,%1,%2,%3};"
                         : "+f"(c1[0]), "+f"(c1[1]), "+f"(c1[2]), "+f"(c1[3])
                         : "r"(a[ks][0]), "r"(a[ks][1]), "r"(a[ks][2]), "r"(a[ks][3]),
                           "r"(b2), "r"(b3));
        }
        *(__half2*)(ob + (size_t)(m0 + g)     * NPIX + n * 8 + 2 * t)       = __floats2half2_rn(c0[0], c0[1]);
        *(__half2*)(ob + (size_t)(m0 + g + 8) * NPIX + n * 8 + 2 * t)       = __floats2half2_rn(c0[2], c0[3]);
        *(__half2*)(ob + (size_t)(m0 + g)     * NPIX + (n + 1) * 8 + 2 * t) = __floats2half2_rn(c1[0], c1[1]);
        *(__half2*)(ob + (size_t)(m0 + g + 8) * NPIX + (n + 1) * 8 + 2 * t) = __floats2half2_rn(c1[2], c1[3]);
    }
}

// ============================================================
// K2: depthwise 3x3, pad 1. DWROWS=16, fp16 smem staging
// (halo overhead 12.5%, smem 9.2 KB -> high occupancy).
// ============================================================
#define DWROWS 16
__global__ __launch_bounds__(256) void k_dw(const float* __restrict__ w) {
    const int tilesY = HH / DWROWS;                 // 16
    const int ytile = blockIdx.x & (tilesY - 1);
    const int ch    = (blockIdx.x / tilesY) % C3;
    const int b     = blockIdx.x / (tilesY * C3);
    const int tid   = threadIdx.x;

    const __half* in  = g_qkv + ((size_t)b * C3 + ch) * NPIX;
    __half*       out = g_dw  + ((size_t)b * C3 + ch) * NPIX;

    __shared__ __half rows[DWROWS + 2][WW];
    const int y0 = ytile * DWROWS;
    for (int i = tid; i < (DWROWS + 2) * (WW / 8); i += 256) {
        int r = i / (WW / 8), c8 = i % (WW / 8);
        int y = y0 - 1 + r;
        if (y >= 0 && y < HH)
            *(uint4*)&rows[r][c8 * 8] = *(const uint4*)(in + y * WW + c8 * 8);
        else {
            uint4 z = {0, 0, 0, 0};
            *(uint4*)&rows[r][c8 * 8] = z;
        }
    }
    __syncthreads();

    const float w00 = w[ch*9+0], w01 = w[ch*9+1], w02 = w[ch*9+2];
    const float w10 = w[ch*9+3], w11 = w[ch*9+4], w12 = w[ch*9+5];
    const float w20 = w[ch*9+6], w21 = w[ch*9+7], w22 = w[ch*9+8];

    const int half = tid >> 7;           // row interleave 0/1
    const int c2   = tid & 127;          // column-pair index
    const int col0 = 2 * c2, col1 = col0 + 1;
    const float lm = (c2 > 0) ? 1.f : 0.f;
    const float rm = (c2 < 127) ? 1.f : 0.f;
    const int xl = max(col0 - 1, 0), xr = min(col1 + 1, WW - 1);

#pragma unroll
    for (int rr = 0; rr < DWROWS / 2; rr++) {
        const int r = 2 * rr + half;
        const __half* r0 = rows[r], *r1 = rows[r + 1], *r2 = rows[r + 2];
        float a0 = __half2float(r0[xl]) * lm, b0 = __half2float(r0[col0]),
              c0v = __half2float(r0[col1]), d0 = __half2float(r0[xr]) * rm;
        float a1 = __half2float(r1[xl]) * lm, b1 = __half2float(r1[col0]),
              c1v = __half2float(r1[col1]), d1 = __half2float(r1[xr]) * rm;
        float a2 = __half2float(r2[xl]) * lm, b2 = __half2float(r2[col0]),
              c2v = __half2float(r2[col1]), d2 = __half2float(r2[xr]) * rm;
        float acc0 = w00*a0 + w01*b0 + w02*c0v + w10*a1 + w11*b1 + w12*c1v + w20*a2 + w21*b2 + w22*c2v;
        float acc1 = w00*b0 + w01*c0v + w02*d0 + w10*b1 + w11*c1v + w12*d1 + w20*b2 + w21*c2v + w22*d2;
        *(__half2*)(out + (y0 + r) * WW + col0) = __floats2half2_rn(acc0, acc1);
    }
}

// ============================================================
// K3: Gram via mma + reg prefetch + fused attn tail (R15 WIN).
// ============================================================
__global__ void __launch_bounds__(192) k_gram(const float* __restrict__ proj,
                                              const float* __restrict__ temp) {
    __shared__ __half Qs[C][136];
    __shared__ __half Ks[C][136];
    __shared__ int isLast;
    const int tid  = threadIdx.x;
    const int warp = tid >> 5, lane = tid & 31;
    const int b    = blockIdx.x >> 6;
    const int px0  = (blockIdx.x & 63) << 10;

    const __half* Q = g_dw + (size_t)b * C3 * NPIX;
    const __half* K = Q + (size_t)C * NPIX;

    const int m0     = (warp >> 1) * 16;
    const int n0base = (warp & 1) * 24;
    float c[3][4] = {{0.f}};
    float sq = 0.f;
    const int nch = tid % 96, npart = tid / 96;

    for (int i = tid; i < C * 16; i += 192) {
        int k = i >> 4, q = i & 15;
        *(uint4*)&Qs[k][q * 8] = *(const uint4*)(Q + (size_t)k * NPIX + px0 + q * 8);
        *(uint4*)&Ks[k][q * 8] = *(const uint4*)(K + (size_t)k * NPIX + px0 + q * 8);
    }
    __syncthreads();

#pragma unroll 1
    for (int chk = 0; chk < 8; chk++) {
        uint4 pq[4], pk[4];
        if (chk < 7) {
            const int tb = px0 + (chk + 1) * 128;
#pragma unroll
            for (int j = 0; j < 4; j++) {
                int i = tid + j * 192;
                int k = i >> 4, q = i & 15;
                pq[j] = *(const uint4*)(Q + (size_t)k * NPIX + tb + q * 8);
                pk[j] = *(const uint4*)(K + (size_t)k * NPIX + tb + q * 8);
            }
        }

        {
            const __half2* r2 = (const __half2*)(((nch < C) ? Qs[nch] : Ks[nch - C]) + npart * 64);
#pragma unroll
            for (int j = 0; j < 32; j++) {
                float2 f = __half22float2(r2[j]);
                sq += f.x * f.x + f.y * f.y;
            }
        }

#pragma unroll
        for (int ks = 0; ks < 8; ks++) {
            u32 a0r, a1r, a2r, a3r;
            u32 aaddr = smem_u32(&Qs[m0 + (lane & 15)][ks * 16 + (lane >> 4) * 8]);
            asm volatile("ldmatrix.sync.aligned.m8n8.x4.shared.b16 {%0,%1,%2,%3}, [%4];"
                         : "=r"(a0r), "=r"(a1r), "=r"(a2r), "=r"(a3r) : "r"(aaddr));
#pragma unroll
            for (int j = 0; j < 3; j++) {
                const int n0 = n0base + j * 8;
                u32 b0, b1;
                u32 baddr = smem_u32(&Ks[n0 + (lane & 7)][ks * 16 + ((lane >> 3) & 1) * 8]);
                asm volatile("ldmatrix.sync.aligned.m8n8.x2.shared.b16 {%0,%1}, [%2];"
                             : "=r"(b0), "=r"(b1) : "r"(baddr));
                asm volatile("mma.sync.aligned.m16n8k16.row.col.f32.f16.f16.f32 "
                             "{%0,%1,%2,%3}, {%4,%5,%6,%7}, {%8,%9}, {%0,%1,%2,%3};"
                             : "+f"(c[j][0]), "+f"(c[j][1]), "+f"(c[j][2]), "+f"(c[j][3])
                             : "r"(a0r), "r"(a1r), "r"(a2r), "r"(a3r), "r"(b0), "r"(b1));
            }
        }
        __syncthreads();
        if (chk < 7) {
#pragma unroll
            for (int j = 0; j < 4; j++) {
                int i = tid + j * 192;
                int k = i >> 4, q = i & 15;
                *(uint4*)&Qs[k][q * 8] = pq[j];
                *(uint4*)&Ks[k][q * 8] = pk[j];
            }
            __syncthreads();
        }
    }

    float* gbase = g_small + b * (C * C + 2 * C);
    const int g = lane >> 2, t = lane & 3;
#pragma unroll
    for (int j = 0; j < 3; j++) {
        const int n0 = n0base + j * 8;
        atomicAdd(&gbase[(m0 + g)     * C + n0 + 2 * t],     c[j][0]);
        atomicAdd(&gbase[(m0 + g)     * C + n0 + 2 * t + 1], c[j][1]);
        atomicAdd(&gbase[(m0 + g + 8) * C + n0 + 2 * t],     c[j][2]);
        atomicAdd(&gbase[(m0 + g + 8) * C + n0 + 2 * t + 1], c[j][3]);
    }
    atomicAdd(&gbase[C * C + nch], sq);

    __threadfence();
    if (tid == 0) isLast = (atomicAdd(&g_cnt[b], 1) == 63) ? 1 : 0;
    __syncthreads();
    if (!isLast) return;

    float (*A)[C + 1] = (float(*)[C + 1])Qs;
    float* P  = (float*)Ks;
    float* qn = P + C * C;
    float* kn = qn + C;
    const volatile float* gb = gbase;
    const float T = temp[0];

    for (int i = tid; i < C * C; i += 192) P[i] = proj[i];
    if (tid < C)          qn[tid]     = fmaxf(sqrtf(gb[C * C + tid]), 1e-12f);
    else if (tid < 2 * C) kn[tid - C] = fmaxf(sqrtf(gb[C * C + tid]), 1e-12f);
    __syncthreads();

    for (int i = tid; i < C * C; i += 192) {
        int r = i / C, d = i % C;
        A[r][d] = gb[i] * T / (qn[r] * kn[d]);
    }
    __syncthreads();

    for (int r = warp; r < C; r += 6) {
        float v0 = A[r][lane];
        float v1 = (lane + 32 < C) ? A[r][lane + 32] : -1e30f;
        float mx = fmaxf(v0, v1);
#pragma unroll
        for (int o = 16; o > 0; o >>= 1) mx = fmaxf(mx, __shfl_xor_sync(~0u, mx, o));
        float e0 = expf(v0 - mx);
        float e1 = (lane + 32 < C) ? expf(v1 - mx) : 0.f;
        float s = e0 + e1;
#pragma unroll
        for (int o = 16; o > 0; o >>= 1) s += __shfl_xor_sync(~0u, s, o);
        float inv = 1.f / s;
        A[r][lane] = e0 * inv;
        if (lane + 32 < C) A[r][lane + 32] = e1 * inv;
    }
    __syncthreads();

    float* Mb = g_M + b * C * C;
    for (int oc = warp; oc < C; oc += 6) {
        float acc0 = 0.f, acc1 = 0.f;
#pragma unroll 8
        for (int cc = 0; cc < C; cc++) {
            float p = P[oc * C + cc];
            acc0 += p * A[cc][lane];
            acc1 += p * A[cc][(lane & 15) + 32];
        }
        Mb[oc * C + lane] = acc0;
        if (lane < 16) Mb[oc * C + 32 + lane] = acc1;
    }
}

// ============================================================
// K5: out = M @ V via mma (reverted to R14 x2.trans form:
// 25.8us, occ 70% — the x4 variant cost regs/occupancy).
// ============================================================
__global__ void __launch_bounds__(192) k_out(float* __restrict__ out) {
    __shared__ __half Ms[C][56];
    __shared__ __half Vs[C][136];
    const int tid  = threadIdx.x;
    const int warp = tid >> 5, lane = tid & 31;
    const int b    = blockIdx.x >> 9;
    const int px0  = (blockIdx.x & 511) << 7;

    const float* Mb = g_M + b * C * C;
    for (int i = tid; i < C * C; i += 192)
        Ms[i / C][i % C] = __float2half_rn(Mb[i]);
    const __half* vb = g_dw + (size_t)b * C3 * NPIX + (size_t)(2 * C) * NPIX + px0;
    for (int i = tid; i < C * 16; i += 192) {
        int k = i >> 4, q = i & 15;
        *(uint4*)&Vs[k][q * 8] = *(const uint4*)(vb + (size_t)k * NPIX + q * 8);
    }
    __syncthreads();

    const int m0 = (warp >> 1) * 16;
    u32 a[3][4];
#pragma unroll
    for (int ks = 0; ks < 3; ks++) {
        u32 addr = smem_u32(&Ms[m0 + (lane & 15)][ks * 16 + (lane >> 4) * 8]);
        asm volatile("ldmatrix.sync.aligned.m8n8.x4.shared.b16 {%0,%1,%2,%3}, [%4];"
                     : "=r"(a[ks][0]), "=r"(a[ks][1]), "=r"(a[ks][2]), "=r"(a[ks][3])
                     : "r"(addr));
    }

    float* ob = out + (size_t)b * C * NPIX + px0;
    const int g = lane >> 2, t = lane & 3;
#pragma unroll 4
    for (int j = 0; j < 8; j++) {
        const int n = (warp & 1) * 8 + j;
        float c0 = 0.f, c1 = 0.f, c2 = 0.f, c3 = 0.f;
#pragma unroll
        for (int ks = 0; ks < 3; ks++) {
            u32 b0, b1;
            u32 baddr = smem_u32(&Vs[ks * 16 + (lane & 15)][n * 8]);
            asm volatile("ldmatrix.sync.aligned.m8n8.x2.trans.shared.b16 {%0,%1}, [%2];"
                         : "=r"(b0), "=r"(b1) : "r"(baddr));
            asm volatile("mma.sync.aligned.m16n8k16.row.col.f32.f16.f16.f32 "
                         "{%0,%1,%2,%3}, {%4,%5,%6,%7}, {%8,%9}, {%0,%1,%2,%3};"
                         : "+f"(c0), "+f"(c1), "+f"(c2), "+f"(c3)
                         : "r"(a[ks][0]), "r"(a[ks][1]), "r"(a[ks][2]), "r"(a[ks][3]),
                           "r"(b0), "r"(b1));
        }
        *(float2*)(ob + (size_t)(m0 + g)     * NPIX + n * 8 + 2 * t) = make_float2(c0, c1);
        *(float2*)(ob + (size_t)(m0 + g + 8) * NPIX + n * 8 + 2 * t) = make_float2(c2, c3);
    }
}

// ============================================================
extern "C" void kernel_launch(void* const* d_in, const int* in_sizes, int n_in,
                              void* d_out, int out_size) {
    const float* x      = (const float*)d_in[0];
    const float* qkv_w  = (const float*)d_in[1];
    const float* dw_w   = (const float*)d_in[2];
    const float* proj_w = (const float*)d_in[3];
    const float* temp   = (const float*)d_in[4];

    void* smallp = nullptr;
    cudaGetSymbolAddress(&smallp, g_small);
    cudaMemsetAsync(smallp, 0, sizeof(float) * Bc * (C * C + 2 * C));
    void* cntp = nullptr;
    cudaGetSymbolAddress(&cntp, g_cnt);
    cudaMemsetAsync(cntp, 0, sizeof(int) * Bc);

    k_qkv <<<Bc * 512,                288>>>(x, qkv_w);
    k_dw  <<<Bc * C3 * (HH / DWROWS), 256>>>(dw_w);
    k_gram<<<Bc * 64,                 192>>>(proj_w, temp);
    k_out <<<Bc * 512,                192>>>((float*)d_out);
}